// round 14
// baseline (speedup 1.0000x reference)
#include <cuda_runtime.h>
#include <math.h>

#define BB 2
#define TT 8
#define HH 256
#define WW 512
#define NPIX (TT*HH*WW)        // 1048576
#define KM 8
#define NSEG (BB*KM)           // 16
#define NB 2048                // bins over dist in [0,1)
#define CHUNKS 222             // k_main blocks per batch (3/SM, one wave = 444)
#define HW (KM*NB/2)           // u16-packed words per block hist = 8192 (32KB)
#define NQ (NPIX/4)            // 262144 quads
#define SG 256                 // k_stats blocks per batch -> 4 quads (16 px) per thread

// ---------------- static device scratch (zero-initialized at load) ----------------
__device__ unsigned int d_histneg[NSEG * NB];
__device__ unsigned int d_histpos[NSEG * NB];
__device__ int    d_cnt[NSEG];
__device__ int    d_sit[NSEG], d_siy[NSEG], d_six[NSEG];
__device__ double d_ssig[NSEG], d_ssig2[NSEG];
__device__ double d_seedbg[BB], d_seedfg[BB];
__device__ float  d_A[NSEG], d_m0[NSEG], d_m1[NSEG], d_m2[NSEG], d_D[NSEG];
__device__ float  d_var[NSEG], d_pres[NSEG];
__device__ double d_inst[NSEG];
__device__ int    d_done;      // reset by k_lovasz finisher
__device__ int    c_stats;     // reset by k_stats finisher

#define DT_STEP ((float)(0.1 / 31.0))
#define DY_STEP ((float)(1.6 / 799.0))
#define DX_STEP ((float)(4.16 / 1999.0))
#define L2E 1.4426950408889634f

__device__ __forceinline__ float tanh_fast(float x) {
    float r; asm("tanh.approx.f32 %0, %1;" : "=f"(r) : "f"(x)); return r;
}
__device__ __forceinline__ float ex2_fast(float x) {
    float r; asm("ex2.approx.f32 %0, %1;" : "=f"(r) : "f"(x)); return r;
}
__inline__ __device__ double warpSumD(double v) {
    #pragma unroll
    for (int o = 16; o > 0; o >>= 1) v += __shfl_down_sync(0xffffffffu, v, o);
    return v;
}
__inline__ __device__ float warpSumF(float v) {
    #pragma unroll
    for (int o = 16; o > 0; o >>= 1) v += __shfl_down_sync(0xffffffffu, v, o);
    return v;
}

// ---------------- K1: zero hists + masked statistics + finalize ----------------
// 16 pixels/thread, 512 blocks (grid-limited occupancy fix); REDUX int tails.
__global__ void __launch_bounds__(256, 4)
k_stats(const float* __restrict__ pred, const int* __restrict__ inst) {
    int b = blockIdx.y;
    int tid = threadIdx.x;
    // zero atomically-accumulated buffers used by LATER kernels
    {
        int id = (blockIdx.y * gridDim.x + blockIdx.x) * 256 + tid;  // 0..131071
        if (id < NSEG * NB) d_histpos[id] = 0u;
        else if (id < 2 * NSEG * NB) d_histneg[id - NSEG * NB] = 0u;
        if (id < BB) { d_seedbg[id] = 0.0; d_seedfg[id] = 0.0; }
    }

    const float4* sig = (const float4*)(pred + ((size_t)b * 5 + 3) * NPIX);
    const int4*   ib  = (const int4*)(inst + (size_t)b * NPIX);

    // packed: acc1 = (cnt<<24)|(sum_t<<16)|sum_y  (cnt<=16, sum_t<=112, sum_y<=4080)
    int   acc1[KM], accx[KM];
    float s1[KM], s2[KM];
    #pragma unroll
    for (int k = 0; k < KM; k++) { acc1[k]=0; accx[k]=0; s1[k]=0.f; s2[k]=0.f; }

    int gid = blockIdx.x * 256 + tid;   // 0..65535; 4 quads/thread

    #pragma unroll
    for (int batch = 0; batch < 2; batch++) {
        // front-batch 2 quads (4 loads)
        int4   v4[2];
        float4 f4[2];
        #pragma unroll
        for (int i = 0; i < 2; i++) {
            int q = gid + (batch * 2 + i) * (SG * 256);
            v4[i] = ib[q];
            f4[i] = sig[q];
        }
        #pragma unroll
        for (int i = 0; i < 2; i++) {
            int q = gid + (batch * 2 + i) * (SG * 256);
            int p = q * 4;
            int t = p >> 17, y = (p >> 9) & 255, x0 = p & 511;
            int hdr = (1 << 24) | (t << 16) | y;
            int   vv[4] = {v4[i].x, v4[i].y, v4[i].z, v4[i].w};
            float ff[4] = {f4[i].x, f4[i].y, f4[i].z, f4[i].w};
            #pragma unroll
            for (int j = 0; j < 4; j++) {
                int v = vv[j]; float s = ff[j]; float ss = s * s; int x = x0 + j;
                #pragma unroll
                for (int k = 0; k < KM; k++) {
                    if (v == k + 1) { acc1[k] += hdr; accx[k] += x; s1[k] += s; s2[k] += ss; }
                }
            }
        }
    }

    int lane = tid & 31;
    #pragma unroll
    for (int k = 0; k < KM; k++) {
        int cnt = (unsigned)acc1[k] >> 24;
        int it  = (acc1[k] >> 16) & 0xff;
        int iy  = acc1[k] & 0xffff;
        int pci = (cnt << 16) | it;          // warp sums: cnt<=512, it<=3584 -> both fit
        // hardware warp reductions for ints
        pci = __reduce_add_sync(0xffffffffu, pci);
        iy  = __reduce_add_sync(0xffffffffu, iy);
        int ix = __reduce_add_sync(0xffffffffu, accx[k]);
        // float chains (independent across k)
        float v1 = warpSumF(s1[k]);
        float v2 = warpSumF(s2[k]);
        if (lane == 0 && pci > 0) {
            int seg = b * KM + k;
            atomicAdd(&d_cnt[seg], pci >> 16);
            atomicAdd(&d_sit[seg], pci & 0xffff);
            atomicAdd(&d_siy[seg], iy);
            atomicAdd(&d_six[seg], ix);
            atomicAdd(&d_ssig[seg],  (double)v1);
            atomicAdd(&d_ssig2[seg], (double)v2);
        }
    }

    // fused finalize: last block computes folded per-k constants
    __threadfence();
    __shared__ int is_last;
    if (tid == 0) {
        int prev = atomicAdd(&c_stats, 1);
        is_last = (prev == (int)(gridDim.x * gridDim.y) - 1) ? 1 : 0;
    }
    __syncthreads();
    if (is_last) {
        if (tid == 0) c_stats = 0;
        if (tid < NSEG) {
            int s = tid;
            double cnt2 = (double)d_cnt[s];
            double safe = cnt2 > 0.0 ? cnt2 : 1.0;
            double ct = (0.1 / 31.0)    * (double)d_sit[s] / safe;
            double cy = (1.6 / 799.0)   * (double)d_siy[s] / safe;
            double cx = (4.16 / 1999.0) * (double)d_six[s] / safe;
            double sm = d_ssig[s]  / safe;
            double sq2 = d_ssig2[s] / safe;
            double sexp = exp(10.0 * sm);
            double A = -sexp * (double)L2E;            // f = A*sq + log2(NB)
            double c2 = ct*ct + cy*cy + cx*cx;
            d_A[s]  = (float)A;
            d_m0[s] = (float)(-2.0 * A * ct);
            d_m1[s] = (float)(-2.0 * A * cy);
            d_m2[s] = (float)(-2.0 * A * cx);
            d_D[s]  = (float)(A * c2 + 11.0);          // log2(2048) = 11
            d_var[s]  = (float)(sq2 - sm * sm);
            d_pres[s] = (cnt2 > 0.0) ? 1.0f : 0.0f;
        }
    }
}

// ---------------- K2: main pass, all-k smem hist, direct atomic flush (verbatim) ----------------
__global__ void __launch_bounds__(256, 3)
k_main(const float* __restrict__ pred, const int* __restrict__ inst) {
    __shared__ unsigned int sh[HW];   // 32KB u16-packed neg hist
    int b = blockIdx.y;
    int tid = threadIdx.x;
    #pragma unroll
    for (int i = 0; i < HW / 256; i++) sh[tid + i * 256] = 0u;

    float vA[KM], vm0[KM], vm1[KM], vm2[KM], vD[KM];
    #pragma unroll
    for (int k = 0; k < KM; k++) {
        int s = b * KM + k;
        vA[k]=d_A[s]; vm0[k]=d_m0[s]; vm1[k]=d_m1[s]; vm2[k]=d_m2[s]; vD[k]=d_D[s];
    }
    __syncthreads();

    const float* p0 = pred + (size_t)b * 5 * NPIX;
    const float4* ch0 = (const float4*)p0;
    const float4* ch1 = (const float4*)(p0 + NPIX);
    const float4* ch2 = (const float4*)(p0 + 2 * NPIX);
    const float4* ch4 = (const float4*)(p0 + 4 * NPIX);
    const int4*   ib  = (const int4*)(inst + (size_t)b * NPIX);
    unsigned int* hpos = d_histpos + b * KM * NB;
    unsigned int* hneg = d_histneg + b * KM * NB;

    double fg = 0.0, bg = 0.0;
    int gid = blockIdx.x * 256 + tid;

    #pragma unroll
    for (int i = 0; i < 5; i++) {
        int q = gid + i * (CHUNKS * 256);
        if (q < NQ) {
            float4 a4 = ch0[q];
            float4 b4 = ch1[q];
            float4 c4 = ch2[q];
            float4 s4 = ch4[q];
            int4   v4 = ib[q];
            int p = q * 4;
            float tc = (float)(p >> 17) * DT_STEP;
            float yc = (float)((p >> 9) & 255) * DY_STEP;
            float xc = (float)(p & 511) * DX_STEP;

            float aa[4]  = {a4.x, a4.y, a4.z, a4.w};
            float bb2[4] = {b4.x, b4.y, b4.z, b4.w};
            float cc[4]  = {c4.x, c4.y, c4.z, c4.w};
            float ssv[4] = {s4.x, s4.y, s4.z, s4.w};
            int   vv[4]  = {v4.x, v4.y, v4.z, v4.w};

            #pragma unroll
            for (int j = 0; j < 4; j++) {
                float e0 = tanh_fast(aa[j]) + tc;
                float e1 = tanh_fast(bb2[j]) + yc;
                float e2 = tanh_fast(cc[j]) + xc + (float)j * DX_STEP;
                float ee = e0*e0 + e1*e1 + e2*e2;
                float seed = fmaf(tanh_fast(0.5f * ssv[j]), 0.5f, 0.5f);
                int iv = vv[j];
                if (iv == 0) bg += (double)(seed * seed);

                #pragma unroll
                for (int k = 0; k < KM; k++) {
                    float f = fmaf(vA[k], ee,
                              fmaf(e0, vm0[k],
                              fmaf(e1, vm1[k],
                              fmaf(e2, vm2[k], vD[k]))));
                    float g = ex2_fast(f);      // = NB * dist
                    if (iv == k + 1) {
                        float dist = g * (1.0f / (float)NB);
                        float df = seed - dist;
                        fg += (double)(df * df);
                        int bp = min((int)((1.0f - dist) * (float)NB), NB - 1);
                        if (bp > 0) atomicAdd(&hpos[k * NB + bp], 1u);
                    } else {
                        int bn = min((int)g, NB - 1);
                        if (bn > 0)
                            atomicAdd(&sh[k * (NB / 2) + (bn >> 1)],
                                      1u << ((bn & 1) << 4));
                    }
                }
            }
        }
    }
    __syncthreads();

    // flush private hist DIRECTLY into global hist: atomics only on nonzero words
    #pragma unroll
    for (int i = 0; i < HW / 256; i++) {
        int w = tid + i * 256;              // packed word = k*(NB/2) + (bin>>1)
        unsigned v = sh[w];
        if (v) {
            int k    = w >> 10;             // NB/2 = 1024 words per k
            int bin2 = (w & 1023) * 2;
            unsigned lo = v & 0xffffu, hi = v >> 16;
            unsigned* dsth = &hneg[k * NB + bin2];
            if (lo) atomicAdd(dsth,     lo);
            if (hi) atomicAdd(dsth + 1, hi);
        }
    }

    fg = warpSumD(fg); bg = warpSumD(bg);
    __shared__ double wfg[8], wbg[8];
    int wid = tid >> 5, lid = tid & 31;
    if (lid == 0) { wfg[wid] = fg; wbg[wid] = bg; }
    __syncthreads();
    if (wid == 0) {
        double f2s = (lid < 8) ? wfg[lid] : 0.0;
        double b2s = (lid < 8) ? wbg[lid] : 0.0;
        f2s = warpSumD(f2s); b2s = warpSumD(b2s);
        if (lid == 0) { atomicAdd(&d_seedfg[b], f2s); atomicAdd(&d_seedbg[b], b2s); }
    }
}

// ---------------- K3: Lovász, low-sync suffix scan + fused combine + reset (verbatim) ----------------
__global__ void k_lovasz(float* out) {
    int seg = blockIdx.x;
    int tid = threadIdx.x;
    int lane = tid & 31, wid = tid >> 5;
    int Pi = d_cnt[seg];
    float v_out = 0.0f;

    if (Pi > 0) {
        float P = (float)Pi;
        const uint4* hp4 = (const uint4*)(d_histpos + seg * NB);
        const uint4* hn4 = (const uint4*)(d_histneg + seg * NB);
        const int CH = NB / 256;   // 8
        int lo = tid * CH;
        uint4 pa = hp4[2 * tid], pb = hp4[2 * tid + 1];
        uint4 na = hn4[2 * tid], nb2 = hn4[2 * tid + 1];
        int hpv[CH] = {(int)pa.x,(int)pa.y,(int)pa.z,(int)pa.w,
                       (int)pb.x,(int)pb.y,(int)pb.z,(int)pb.w};
        int hnv[CH] = {(int)na.x,(int)na.y,(int)na.z,(int)na.w,
                       (int)nb2.x,(int)nb2.y,(int)nb2.z,(int)nb2.w};
        int cp = 0, cn = 0;
        #pragma unroll
        for (int j = 0; j < CH; j++) { cp += hpv[j]; cn += hnv[j]; }

        int incP = cp, incN = cn;
        #pragma unroll
        for (int o = 1; o < 32; o <<= 1) {
            int tP = __shfl_down_sync(0xffffffffu, incP, o);
            int tN = __shfl_down_sync(0xffffffffu, incN, o);
            if (lane + o < 32) { incP += tP; incN += tN; }
        }
        __shared__ int wP[8], wN[8];
        if (lane == 0) { wP[wid] = incP; wN[wid] = incN; }
        __syncthreads();
        int laterP = 0, laterN = 0;
        #pragma unroll
        for (int u = 0; u < 8; u++) {
            if (u > wid) { laterP += wP[u]; laterN += wN[u]; }
        }
        int supP = incP - cp + laterP;
        int supN = incN - cn + laterN;

        float jsum = 0.0f;
        int p = supP, n = supN;
        #pragma unroll
        for (int j = CH - 1; j >= 0; j--) {
            p += hpv[j]; n += hnv[j];
            if (lo + j >= 1) jsum += __fdividef((float)(p + n), P + (float)n);
        }
        jsum = warpSumF(jsum);
        __shared__ float wj[8];
        if (lane == 0) wj[wid] = jsum;
        __syncthreads();
        if (wid == 0) {
            float v = (lane < 8) ? wj[lane] : 0.0f;
            v = warpSumF(v);
            if (lane == 0) v_out = v;
        }
    }

    __shared__ int is_fin;
    if (tid == 0) {
        d_inst[seg] = (Pi > 0) ? ((double)v_out + 0.5) * (2.0 / (double)NB) : 0.0;
        __threadfence();
        int prev = atomicAdd(&d_done, 1);
        is_fin = (prev == NSEG - 1) ? 1 : 0;
    }
    __syncthreads();
    if (is_fin) {
        if (tid == 0) {
            double tot = 0.0;
            for (int b = 0; b < BB; b++) {
                double obj = 0.0, il = 0.0, vl = 0.0;
                for (int k = 0; k < KM; k++) {
                    int s = b * KM + k;
                    double pr = (double)d_pres[s];
                    obj += pr;
                    il += d_inst[s] * pr;
                    vl += (double)d_var[s] * pr;
                }
                double so = obj > 0.0 ? obj : 1.0;
                double seedl = (d_seedbg[b] + d_seedfg[b]) / (double)(HH * WW);
                tot += (il / so) + 10.0 * (vl / so) + seedl;
            }
            out[0] = (float)(tot / (double)BB);
            d_done = 0;
        }
        if (tid < NSEG) {
            d_cnt[tid] = 0; d_sit[tid] = 0; d_siy[tid] = 0; d_six[tid] = 0;
            d_ssig[tid] = 0.0; d_ssig2[tid] = 0.0;
        }
    }
}

// ---------------- launch ----------------
extern "C" void kernel_launch(void* const* d_in, const int* in_sizes, int n_in,
                              void* d_out, int out_size) {
    const float* pred = (const float*)d_in[0];
    const int*   inst = (const int*)d_in[1];
    (void)in_sizes; (void)n_in; (void)out_size;

    dim3 g1(SG, BB);
    k_stats<<<g1, 256>>>(pred, inst);

    dim3 g3(CHUNKS, BB);
    k_main<<<g3, 256>>>(pred, inst);

    k_lovasz<<<NSEG, 256>>>((float*)d_out);
}

// round 15
// speedup vs baseline: 1.2461x; 1.2461x over previous
#include <cuda_runtime.h>
#include <math.h>

#define BB 2
#define TT 8
#define HH 256
#define WW 512
#define NPIX (TT*HH*WW)        // 1048576
#define KM 8
#define NSEG (BB*KM)           // 16
#define NB 2048                // bins over dist in [0,1)
#define CHUNKS 222             // k_main blocks per batch (3/SM, one wave = 444)
#define HW (KM*NB/2)           // u16-packed words per block hist = 8192 (32KB)
#define NQ (NPIX/4)            // 262144 quads
#define SG 128                 // k_stats blocks per batch -> 8 quads (32 px) per thread

// ---------------- static device scratch (zero-initialized at load) ----------------
__device__ unsigned int d_histneg[NSEG * NB];
__device__ unsigned int d_histpos[NSEG * NB];
__device__ int    d_cnt[NSEG];
__device__ int    d_sit[NSEG], d_siy[NSEG], d_six[NSEG];
__device__ double d_ssig[NSEG], d_ssig2[NSEG];
__device__ double d_seedbg[BB], d_seedfg[BB];
__device__ float  d_A[NSEG], d_m0[NSEG], d_m1[NSEG], d_m2[NSEG], d_D[NSEG];
__device__ float  d_var[NSEG], d_pres[NSEG];
__device__ double d_inst[NSEG];
__device__ int    d_done;      // reset by k_lovasz finisher
__device__ int    c_stats;     // reset by k_stats finisher

#define DT_STEP ((float)(0.1 / 31.0))
#define DY_STEP ((float)(1.6 / 799.0))
#define DX_STEP ((float)(4.16 / 1999.0))
#define L2E 1.4426950408889634f

__device__ __forceinline__ float tanh_fast(float x) {
    float r; asm("tanh.approx.f32 %0, %1;" : "=f"(r) : "f"(x)); return r;
}
__device__ __forceinline__ float ex2_fast(float x) {
    float r; asm("ex2.approx.f32 %0, %1;" : "=f"(r) : "f"(x)); return r;
}
__inline__ __device__ double warpSumD(double v) {
    #pragma unroll
    for (int o = 16; o > 0; o >>= 1) v += __shfl_down_sync(0xffffffffu, v, o);
    return v;
}
__inline__ __device__ float warpSumF(float v) {
    #pragma unroll
    for (int o = 16; o > 0; o >>= 1) v += __shfl_down_sync(0xffffffffu, v, o);
    return v;
}

// ---------------- K1: zero hists + masked statistics + finalize ----------------
// 32 px/thread; REDUX warp tails; smem BLOCK reduction -> 1 atomic set per (block,k).
__global__ void __launch_bounds__(256, 3)
k_stats(const float* __restrict__ pred, const int* __restrict__ inst) {
    int b = blockIdx.y;
    int tid = threadIdx.x;
    // zero atomically-accumulated buffers used by LATER kernels
    {
        int id = (blockIdx.y * gridDim.x + blockIdx.x) * 256 + tid;  // 0..65535 exactly
        if (id < NSEG * NB) d_histpos[id] = 0u;
        else d_histneg[id - NSEG * NB] = 0u;
        if (id < BB) { d_seedbg[id] = 0.0; d_seedfg[id] = 0.0; }
    }

    const float4* sig = (const float4*)(pred + ((size_t)b * 5 + 3) * NPIX);
    const int4*   ib  = (const int4*)(inst + (size_t)b * NPIX);

    // packed: acc1 = (cnt<<24)|(sum_t<<16)|sum_y  (cnt<=32, sum_t<=224, sum_y<=8160)
    int   acc1[KM], accx[KM];
    float s1[KM], s2[KM];
    #pragma unroll
    for (int k = 0; k < KM; k++) { acc1[k]=0; accx[k]=0; s1[k]=0.f; s2[k]=0.f; }

    int gid = blockIdx.x * 256 + tid;   // 0..32767; 8 quads/thread

    #pragma unroll
    for (int batch = 0; batch < 4; batch++) {
        int4   v4[2];
        float4 f4[2];
        #pragma unroll
        for (int i = 0; i < 2; i++) {
            int q = gid + (batch * 2 + i) * (SG * 256);
            v4[i] = ib[q];
            f4[i] = sig[q];
        }
        #pragma unroll
        for (int i = 0; i < 2; i++) {
            int q = gid + (batch * 2 + i) * (SG * 256);
            int p = q * 4;
            int t = p >> 17, y = (p >> 9) & 255, x0 = p & 511;
            int hdr = (1 << 24) | (t << 16) | y;
            int   vv[4] = {v4[i].x, v4[i].y, v4[i].z, v4[i].w};
            float ff[4] = {f4[i].x, f4[i].y, f4[i].z, f4[i].w};
            #pragma unroll
            for (int j = 0; j < 4; j++) {
                int v = vv[j]; float s = ff[j]; float ss = s * s; int x = x0 + j;
                #pragma unroll
                for (int k = 0; k < KM; k++) {
                    if (v == k + 1) { acc1[k] += hdr; accx[k] += x; s1[k] += s; s2[k] += ss; }
                }
            }
        }
    }

    // warp-level reduction, partials to smem
    __shared__ int   sPCI[8][KM], sIY[8][KM], sIX[8][KM];
    __shared__ float sS1[8][KM], sS2[8][KM];
    int lane = tid & 31, wid = tid >> 5;
    #pragma unroll
    for (int k = 0; k < KM; k++) {
        int cnt = (unsigned)acc1[k] >> 24;
        int it  = (acc1[k] >> 16) & 0xff;
        int iy  = acc1[k] & 0xffff;
        int pci = (cnt << 16) | it;          // warp sums: cnt<=1024, it<=7168 -> fit
        pci = __reduce_add_sync(0xffffffffu, pci);
        iy  = __reduce_add_sync(0xffffffffu, iy);
        int ix = __reduce_add_sync(0xffffffffu, accx[k]);
        float v1 = warpSumF(s1[k]);
        float v2 = warpSumF(s2[k]);
        if (lane == 0) {
            sPCI[wid][k] = pci; sIY[wid][k] = iy; sIX[wid][k] = ix;
            sS1[wid][k] = v1;   sS2[wid][k] = v2;
        }
    }
    __syncthreads();

    // block-level: warp w reduces the 8 warp-partials for k = w, ONE atomic set
    if (wid < KM) {
        int k = wid;
        int pci = 0, iy = 0, ix = 0;
        float v1 = 0.f, v2 = 0.f;
        if (lane < 8) {
            pci = sPCI[lane][k]; iy = sIY[lane][k]; ix = sIX[lane][k];
            v1 = sS1[lane][k];   v2 = sS2[lane][k];
        }
        #pragma unroll
        for (int o = 4; o > 0; o >>= 1) {
            pci += __shfl_down_sync(0xffffffffu, pci, o);
            iy  += __shfl_down_sync(0xffffffffu, iy,  o);
            ix  += __shfl_down_sync(0xffffffffu, ix,  o);
            v1  += __shfl_down_sync(0xffffffffu, v1,  o);
            v2  += __shfl_down_sync(0xffffffffu, v2,  o);
        }
        if (lane == 0 && pci > 0) {
            int seg = b * KM + k;
            atomicAdd(&d_cnt[seg], pci >> 16);
            atomicAdd(&d_sit[seg], pci & 0xffff);
            atomicAdd(&d_siy[seg], iy);
            atomicAdd(&d_six[seg], ix);
            atomicAdd(&d_ssig[seg],  (double)v1);
            atomicAdd(&d_ssig2[seg], (double)v2);
        }
    }

    // fused finalize: last block computes folded per-k constants
    __threadfence();
    __shared__ int is_last;
    if (tid == 0) {
        int prev = atomicAdd(&c_stats, 1);
        is_last = (prev == (int)(gridDim.x * gridDim.y) - 1) ? 1 : 0;
    }
    __syncthreads();
    if (is_last) {
        if (tid == 0) c_stats = 0;
        if (tid < NSEG) {
            int s = tid;
            double cnt2 = (double)d_cnt[s];
            double safe = cnt2 > 0.0 ? cnt2 : 1.0;
            double ct = (0.1 / 31.0)    * (double)d_sit[s] / safe;
            double cy = (1.6 / 799.0)   * (double)d_siy[s] / safe;
            double cx = (4.16 / 1999.0) * (double)d_six[s] / safe;
            double sm = d_ssig[s]  / safe;
            double sq2 = d_ssig2[s] / safe;
            double sexp = exp(10.0 * sm);
            double A = -sexp * (double)L2E;            // f = A*sq + log2(NB)
            double c2 = ct*ct + cy*cy + cx*cx;
            d_A[s]  = (float)A;
            d_m0[s] = (float)(-2.0 * A * ct);
            d_m1[s] = (float)(-2.0 * A * cy);
            d_m2[s] = (float)(-2.0 * A * cx);
            d_D[s]  = (float)(A * c2 + 11.0);          // log2(2048) = 11
            d_var[s]  = (float)(sq2 - sm * sm);
            d_pres[s] = (cnt2 > 0.0) ? 1.0f : 0.0f;
        }
    }
}

// ---------------- K2: main pass, all-k smem hist, direct atomic flush (verbatim) ----------------
__global__ void __launch_bounds__(256, 3)
k_main(const float* __restrict__ pred, const int* __restrict__ inst) {
    __shared__ unsigned int sh[HW];   // 32KB u16-packed neg hist
    int b = blockIdx.y;
    int tid = threadIdx.x;
    #pragma unroll
    for (int i = 0; i < HW / 256; i++) sh[tid + i * 256] = 0u;

    float vA[KM], vm0[KM], vm1[KM], vm2[KM], vD[KM];
    #pragma unroll
    for (int k = 0; k < KM; k++) {
        int s = b * KM + k;
        vA[k]=d_A[s]; vm0[k]=d_m0[s]; vm1[k]=d_m1[s]; vm2[k]=d_m2[s]; vD[k]=d_D[s];
    }
    __syncthreads();

    const float* p0 = pred + (size_t)b * 5 * NPIX;
    const float4* ch0 = (const float4*)p0;
    const float4* ch1 = (const float4*)(p0 + NPIX);
    const float4* ch2 = (const float4*)(p0 + 2 * NPIX);
    const float4* ch4 = (const float4*)(p0 + 4 * NPIX);
    const int4*   ib  = (const int4*)(inst + (size_t)b * NPIX);
    unsigned int* hpos = d_histpos + b * KM * NB;
    unsigned int* hneg = d_histneg + b * KM * NB;

    double fg = 0.0, bg = 0.0;
    int gid = blockIdx.x * 256 + tid;

    #pragma unroll
    for (int i = 0; i < 5; i++) {
        int q = gid + i * (CHUNKS * 256);
        if (q < NQ) {
            float4 a4 = ch0[q];
            float4 b4 = ch1[q];
            float4 c4 = ch2[q];
            float4 s4 = ch4[q];
            int4   v4 = ib[q];
            int p = q * 4;
            float tc = (float)(p >> 17) * DT_STEP;
            float yc = (float)((p >> 9) & 255) * DY_STEP;
            float xc = (float)(p & 511) * DX_STEP;

            float aa[4]  = {a4.x, a4.y, a4.z, a4.w};
            float bb2[4] = {b4.x, b4.y, b4.z, b4.w};
            float cc[4]  = {c4.x, c4.y, c4.z, c4.w};
            float ssv[4] = {s4.x, s4.y, s4.z, s4.w};
            int   vv[4]  = {v4.x, v4.y, v4.z, v4.w};

            #pragma unroll
            for (int j = 0; j < 4; j++) {
                float e0 = tanh_fast(aa[j]) + tc;
                float e1 = tanh_fast(bb2[j]) + yc;
                float e2 = tanh_fast(cc[j]) + xc + (float)j * DX_STEP;
                float ee = e0*e0 + e1*e1 + e2*e2;
                float seed = fmaf(tanh_fast(0.5f * ssv[j]), 0.5f, 0.5f);
                int iv = vv[j];
                if (iv == 0) bg += (double)(seed * seed);

                #pragma unroll
                for (int k = 0; k < KM; k++) {
                    float f = fmaf(vA[k], ee,
                              fmaf(e0, vm0[k],
                              fmaf(e1, vm1[k],
                              fmaf(e2, vm2[k], vD[k]))));
                    float g = ex2_fast(f);      // = NB * dist
                    if (iv == k + 1) {
                        float dist = g * (1.0f / (float)NB);
                        float df = seed - dist;
                        fg += (double)(df * df);
                        int bp = min((int)((1.0f - dist) * (float)NB), NB - 1);
                        if (bp > 0) atomicAdd(&hpos[k * NB + bp], 1u);
                    } else {
                        int bn = min((int)g, NB - 1);
                        if (bn > 0)
                            atomicAdd(&sh[k * (NB / 2) + (bn >> 1)],
                                      1u << ((bn & 1) << 4));
                    }
                }
            }
        }
    }
    __syncthreads();

    // flush private hist DIRECTLY into global hist: atomics only on nonzero words
    #pragma unroll
    for (int i = 0; i < HW / 256; i++) {
        int w = tid + i * 256;              // packed word = k*(NB/2) + (bin>>1)
        unsigned v = sh[w];
        if (v) {
            int k    = w >> 10;             // NB/2 = 1024 words per k
            int bin2 = (w & 1023) * 2;
            unsigned lo = v & 0xffffu, hi = v >> 16;
            unsigned* dsth = &hneg[k * NB + bin2];
            if (lo) atomicAdd(dsth,     lo);
            if (hi) atomicAdd(dsth + 1, hi);
        }
    }

    fg = warpSumD(fg); bg = warpSumD(bg);
    __shared__ double wfg[8], wbg[8];
    int wid = tid >> 5, lid = tid & 31;
    if (lid == 0) { wfg[wid] = fg; wbg[wid] = bg; }
    __syncthreads();
    if (wid == 0) {
        double f2s = (lid < 8) ? wfg[lid] : 0.0;
        double b2s = (lid < 8) ? wbg[lid] : 0.0;
        f2s = warpSumD(f2s); b2s = warpSumD(b2s);
        if (lid == 0) { atomicAdd(&d_seedfg[b], f2s); atomicAdd(&d_seedbg[b], b2s); }
    }
}

// ---------------- K3: Lovász, low-sync suffix scan + fused combine + reset (verbatim) ----------------
__global__ void k_lovasz(float* out) {
    int seg = blockIdx.x;
    int tid = threadIdx.x;
    int lane = tid & 31, wid = tid >> 5;
    int Pi = d_cnt[seg];
    float v_out = 0.0f;

    if (Pi > 0) {
        float P = (float)Pi;
        const uint4* hp4 = (const uint4*)(d_histpos + seg * NB);
        const uint4* hn4 = (const uint4*)(d_histneg + seg * NB);
        const int CH = NB / 256;   // 8
        int lo = tid * CH;
        uint4 pa = hp4[2 * tid], pb = hp4[2 * tid + 1];
        uint4 na = hn4[2 * tid], nb2 = hn4[2 * tid + 1];
        int hpv[CH] = {(int)pa.x,(int)pa.y,(int)pa.z,(int)pa.w,
                       (int)pb.x,(int)pb.y,(int)pb.z,(int)pb.w};
        int hnv[CH] = {(int)na.x,(int)na.y,(int)na.z,(int)na.w,
                       (int)nb2.x,(int)nb2.y,(int)nb2.z,(int)nb2.w};
        int cp = 0, cn = 0;
        #pragma unroll
        for (int j = 0; j < CH; j++) { cp += hpv[j]; cn += hnv[j]; }

        int incP = cp, incN = cn;
        #pragma unroll
        for (int o = 1; o < 32; o <<= 1) {
            int tP = __shfl_down_sync(0xffffffffu, incP, o);
            int tN = __shfl_down_sync(0xffffffffu, incN, o);
            if (lane + o < 32) { incP += tP; incN += tN; }
        }
        __shared__ int wP[8], wN[8];
        if (lane == 0) { wP[wid] = incP; wN[wid] = incN; }
        __syncthreads();
        int laterP = 0, laterN = 0;
        #pragma unroll
        for (int u = 0; u < 8; u++) {
            if (u > wid) { laterP += wP[u]; laterN += wN[u]; }
        }
        int supP = incP - cp + laterP;
        int supN = incN - cn + laterN;

        float jsum = 0.0f;
        int p = supP, n = supN;
        #pragma unroll
        for (int j = CH - 1; j >= 0; j--) {
            p += hpv[j]; n += hnv[j];
            if (lo + j >= 1) jsum += __fdividef((float)(p + n), P + (float)n);
        }
        jsum = warpSumF(jsum);
        __shared__ float wj[8];
        if (lane == 0) wj[wid] = jsum;
        __syncthreads();
        if (wid == 0) {
            float v = (lane < 8) ? wj[lane] : 0.0f;
            v = warpSumF(v);
            if (lane == 0) v_out = v;
        }
    }

    __shared__ int is_fin;
    if (tid == 0) {
        d_inst[seg] = (Pi > 0) ? ((double)v_out + 0.5) * (2.0 / (double)NB) : 0.0;
        __threadfence();
        int prev = atomicAdd(&d_done, 1);
        is_fin = (prev == NSEG - 1) ? 1 : 0;
    }
    __syncthreads();
    if (is_fin) {
        if (tid == 0) {
            double tot = 0.0;
            for (int b = 0; b < BB; b++) {
                double obj = 0.0, il = 0.0, vl = 0.0;
                for (int k = 0; k < KM; k++) {
                    int s = b * KM + k;
                    double pr = (double)d_pres[s];
                    obj += pr;
                    il += d_inst[s] * pr;
                    vl += (double)d_var[s] * pr;
                }
                double so = obj > 0.0 ? obj : 1.0;
                double seedl = (d_seedbg[b] + d_seedfg[b]) / (double)(HH * WW);
                tot += (il / so) + 10.0 * (vl / so) + seedl;
            }
            out[0] = (float)(tot / (double)BB);
            d_done = 0;
        }
        if (tid < NSEG) {
            d_cnt[tid] = 0; d_sit[tid] = 0; d_siy[tid] = 0; d_six[tid] = 0;
            d_ssig[tid] = 0.0; d_ssig2[tid] = 0.0;
        }
    }
}

// ---------------- launch ----------------
extern "C" void kernel_launch(void* const* d_in, const int* in_sizes, int n_in,
                              void* d_out, int out_size) {
    const float* pred = (const float*)d_in[0];
    const int*   inst = (const int*)d_in[1];
    (void)in_sizes; (void)n_in; (void)out_size;

    dim3 g1(SG, BB);
    k_stats<<<g1, 256>>>(pred, inst);

    dim3 g3(CHUNKS, BB);
    k_main<<<g3, 256>>>(pred, inst);

    k_lovasz<<<NSEG, 256>>>((float*)d_out);
}

// round 16
// speedup vs baseline: 1.2704x; 1.0195x over previous
#include <cuda_runtime.h>
#include <math.h>

#define BB 2
#define TT 8
#define HH 256
#define WW 512
#define NPIX (TT*HH*WW)        // 1048576
#define KM 8
#define NSEG (BB*KM)           // 16
#define NB 2048                // bins over dist in [0,1)
#define CHUNKS 222             // k_main blocks per batch (3/SM, one wave = 444)
#define HW (KM*NB/2)           // u16-packed words per block hist = 8192 (32KB)
#define NQ (NPIX/4)            // 262144 quads
#define SG 256                 // k_stats blocks per batch -> 4 quads (16 px) per thread

// ---------------- static device scratch (zero-initialized at load) ----------------
__device__ unsigned int d_histneg[NSEG * NB];
__device__ unsigned int d_histpos[NSEG * NB];
__device__ int    d_cnt[NSEG];
__device__ int    d_sit[NSEG], d_siy[NSEG], d_six[NSEG];
__device__ double d_ssig[NSEG], d_ssig2[NSEG];
__device__ double d_seedbg[BB], d_seedfg[BB];
__device__ float  d_A[NSEG], d_m0[NSEG], d_m1[NSEG], d_m2[NSEG], d_D[NSEG];
__device__ float  d_var[NSEG], d_pres[NSEG];
__device__ double d_inst[NSEG];
__device__ int    d_done;      // reset by k_lovasz finisher
__device__ int    c_stats;     // reset by k_stats finisher

#define DT_STEP ((float)(0.1 / 31.0))
#define DY_STEP ((float)(1.6 / 799.0))
#define DX_STEP ((float)(4.16 / 1999.0))
#define L2E 1.4426950408889634f

__device__ __forceinline__ float tanh_fast(float x) {
    float r; asm("tanh.approx.f32 %0, %1;" : "=f"(r) : "f"(x)); return r;
}
__device__ __forceinline__ float ex2_fast(float x) {
    float r; asm("ex2.approx.f32 %0, %1;" : "=f"(r) : "f"(x)); return r;
}
__inline__ __device__ double warpSumD(double v) {
    #pragma unroll
    for (int o = 16; o > 0; o >>= 1) v += __shfl_down_sync(0xffffffffu, v, o);
    return v;
}
__inline__ __device__ float warpSumF(float v) {
    #pragma unroll
    for (int o = 16; o > 0; o >>= 1) v += __shfl_down_sync(0xffffffffu, v, o);
    return v;
}

// ---------------- K1: zero hists + masked statistics + finalize ----------------
// 16 px/thread, 512 blocks; REDUX warp tails; smem block reduction -> 1 atomic set/(block,k).
__global__ void __launch_bounds__(256, 4)
k_stats(const float* __restrict__ pred, const int* __restrict__ inst) {
    int b = blockIdx.y;
    int tid = threadIdx.x;
    // zero atomically-accumulated buffers used by LATER kernels
    {
        int id = (blockIdx.y * gridDim.x + blockIdx.x) * 256 + tid;  // 0..131071
        if (id < NSEG * NB) d_histpos[id] = 0u;
        else if (id < 2 * NSEG * NB) d_histneg[id - NSEG * NB] = 0u;
        if (id < BB) { d_seedbg[id] = 0.0; d_seedfg[id] = 0.0; }
    }

    const float4* sig = (const float4*)(pred + ((size_t)b * 5 + 3) * NPIX);
    const int4*   ib  = (const int4*)(inst + (size_t)b * NPIX);

    // packed: acc1 = (cnt<<24)|(sum_t<<16)|sum_y  (cnt<=16, sum_t<=112, sum_y<=4080)
    int   acc1[KM], accx[KM];
    float s1[KM], s2[KM];
    #pragma unroll
    for (int k = 0; k < KM; k++) { acc1[k]=0; accx[k]=0; s1[k]=0.f; s2[k]=0.f; }

    int gid = blockIdx.x * 256 + tid;   // 0..65535; 4 quads/thread

    #pragma unroll
    for (int batch = 0; batch < 2; batch++) {
        int4   v4[2];
        float4 f4[2];
        #pragma unroll
        for (int i = 0; i < 2; i++) {
            int q = gid + (batch * 2 + i) * (SG * 256);
            v4[i] = ib[q];
            f4[i] = sig[q];
        }
        #pragma unroll
        for (int i = 0; i < 2; i++) {
            int q = gid + (batch * 2 + i) * (SG * 256);
            int p = q * 4;
            int t = p >> 17, y = (p >> 9) & 255, x0 = p & 511;
            int hdr = (1 << 24) | (t << 16) | y;
            int   vv[4] = {v4[i].x, v4[i].y, v4[i].z, v4[i].w};
            float ff[4] = {f4[i].x, f4[i].y, f4[i].z, f4[i].w};
            #pragma unroll
            for (int j = 0; j < 4; j++) {
                int v = vv[j]; float s = ff[j]; float ss = s * s; int x = x0 + j;
                #pragma unroll
                for (int k = 0; k < KM; k++) {
                    if (v == k + 1) { acc1[k] += hdr; accx[k] += x; s1[k] += s; s2[k] += ss; }
                }
            }
        }
    }

    // warp-level reduction, partials to smem
    __shared__ int   sPCI[8][KM], sIY[8][KM], sIX[8][KM];
    __shared__ float sS1[8][KM], sS2[8][KM];
    int lane = tid & 31, wid = tid >> 5;
    #pragma unroll
    for (int k = 0; k < KM; k++) {
        int cnt = (unsigned)acc1[k] >> 24;
        int it  = (acc1[k] >> 16) & 0xff;
        int iy  = acc1[k] & 0xffff;
        int pci = (cnt << 16) | it;          // warp sums: cnt<=512, it<=3584 -> fit
        pci = __reduce_add_sync(0xffffffffu, pci);
        iy  = __reduce_add_sync(0xffffffffu, iy);
        int ix = __reduce_add_sync(0xffffffffu, accx[k]);
        float v1 = warpSumF(s1[k]);
        float v2 = warpSumF(s2[k]);
        if (lane == 0) {
            sPCI[wid][k] = pci; sIY[wid][k] = iy; sIX[wid][k] = ix;
            sS1[wid][k] = v1;   sS2[wid][k] = v2;
        }
    }
    __syncthreads();

    // block-level: warp w reduces the 8 warp-partials for k = w, ONE atomic set
    if (wid < KM) {
        int k = wid;
        int pci = 0, iy = 0, ix = 0;
        float v1 = 0.f, v2 = 0.f;
        if (lane < 8) {
            pci = sPCI[lane][k]; iy = sIY[lane][k]; ix = sIX[lane][k];
            v1 = sS1[lane][k];   v2 = sS2[lane][k];
        }
        #pragma unroll
        for (int o = 4; o > 0; o >>= 1) {
            pci += __shfl_down_sync(0xffffffffu, pci, o);
            iy  += __shfl_down_sync(0xffffffffu, iy,  o);
            ix  += __shfl_down_sync(0xffffffffu, ix,  o);
            v1  += __shfl_down_sync(0xffffffffu, v1,  o);
            v2  += __shfl_down_sync(0xffffffffu, v2,  o);
        }
        if (lane == 0 && pci > 0) {
            int seg = b * KM + k;
            atomicAdd(&d_cnt[seg], pci >> 16);
            atomicAdd(&d_sit[seg], pci & 0xffff);
            atomicAdd(&d_siy[seg], iy);
            atomicAdd(&d_six[seg], ix);
            atomicAdd(&d_ssig[seg],  (double)v1);
            atomicAdd(&d_ssig2[seg], (double)v2);
        }
    }

    // fused finalize: last block computes folded per-k constants
    __threadfence();
    __shared__ int is_last;
    if (tid == 0) {
        int prev = atomicAdd(&c_stats, 1);
        is_last = (prev == (int)(gridDim.x * gridDim.y) - 1) ? 1 : 0;
    }
    __syncthreads();
    if (is_last) {
        if (tid == 0) c_stats = 0;
        if (tid < NSEG) {
            int s = tid;
            double cnt2 = (double)d_cnt[s];
            double safe = cnt2 > 0.0 ? cnt2 : 1.0;
            double ct = (0.1 / 31.0)    * (double)d_sit[s] / safe;
            double cy = (1.6 / 799.0)   * (double)d_siy[s] / safe;
            double cx = (4.16 / 1999.0) * (double)d_six[s] / safe;
            double sm = d_ssig[s]  / safe;
            double sq2 = d_ssig2[s] / safe;
            double sexp = exp(10.0 * sm);
            double A = -sexp * (double)L2E;            // f = A*sq + log2(NB)
            double c2 = ct*ct + cy*cy + cx*cx;
            d_A[s]  = (float)A;
            d_m0[s] = (float)(-2.0 * A * ct);
            d_m1[s] = (float)(-2.0 * A * cy);
            d_m2[s] = (float)(-2.0 * A * cx);
            d_D[s]  = (float)(A * c2 + 11.0);          // log2(2048) = 11
            d_var[s]  = (float)(sq2 - sm * sm);
            d_pres[s] = (cnt2 > 0.0) ? 1.0f : 0.0f;
        }
    }
}

// ---------------- K2: main pass, all-k smem hist, direct atomic flush (verbatim) ----------------
__global__ void __launch_bounds__(256, 3)
k_main(const float* __restrict__ pred, const int* __restrict__ inst) {
    __shared__ unsigned int sh[HW];   // 32KB u16-packed neg hist
    int b = blockIdx.y;
    int tid = threadIdx.x;
    #pragma unroll
    for (int i = 0; i < HW / 256; i++) sh[tid + i * 256] = 0u;

    float vA[KM], vm0[KM], vm1[KM], vm2[KM], vD[KM];
    #pragma unroll
    for (int k = 0; k < KM; k++) {
        int s = b * KM + k;
        vA[k]=d_A[s]; vm0[k]=d_m0[s]; vm1[k]=d_m1[s]; vm2[k]=d_m2[s]; vD[k]=d_D[s];
    }
    __syncthreads();

    const float* p0 = pred + (size_t)b * 5 * NPIX;
    const float4* ch0 = (const float4*)p0;
    const float4* ch1 = (const float4*)(p0 + NPIX);
    const float4* ch2 = (const float4*)(p0 + 2 * NPIX);
    const float4* ch4 = (const float4*)(p0 + 4 * NPIX);
    const int4*   ib  = (const int4*)(inst + (size_t)b * NPIX);
    unsigned int* hpos = d_histpos + b * KM * NB;
    unsigned int* hneg = d_histneg + b * KM * NB;

    double fg = 0.0, bg = 0.0;
    int gid = blockIdx.x * 256 + tid;

    #pragma unroll
    for (int i = 0; i < 5; i++) {
        int q = gid + i * (CHUNKS * 256);
        if (q < NQ) {
            float4 a4 = ch0[q];
            float4 b4 = ch1[q];
            float4 c4 = ch2[q];
            float4 s4 = ch4[q];
            int4   v4 = ib[q];
            int p = q * 4;
            float tc = (float)(p >> 17) * DT_STEP;
            float yc = (float)((p >> 9) & 255) * DY_STEP;
            float xc = (float)(p & 511) * DX_STEP;

            float aa[4]  = {a4.x, a4.y, a4.z, a4.w};
            float bb2[4] = {b4.x, b4.y, b4.z, b4.w};
            float cc[4]  = {c4.x, c4.y, c4.z, c4.w};
            float ssv[4] = {s4.x, s4.y, s4.z, s4.w};
            int   vv[4]  = {v4.x, v4.y, v4.z, v4.w};

            #pragma unroll
            for (int j = 0; j < 4; j++) {
                float e0 = tanh_fast(aa[j]) + tc;
                float e1 = tanh_fast(bb2[j]) + yc;
                float e2 = tanh_fast(cc[j]) + xc + (float)j * DX_STEP;
                float ee = e0*e0 + e1*e1 + e2*e2;
                float seed = fmaf(tanh_fast(0.5f * ssv[j]), 0.5f, 0.5f);
                int iv = vv[j];
                if (iv == 0) bg += (double)(seed * seed);

                #pragma unroll
                for (int k = 0; k < KM; k++) {
                    float f = fmaf(vA[k], ee,
                              fmaf(e0, vm0[k],
                              fmaf(e1, vm1[k],
                              fmaf(e2, vm2[k], vD[k]))));
                    float g = ex2_fast(f);      // = NB * dist
                    if (iv == k + 1) {
                        float dist = g * (1.0f / (float)NB);
                        float df = seed - dist;
                        fg += (double)(df * df);
                        int bp = min((int)((1.0f - dist) * (float)NB), NB - 1);
                        if (bp > 0) atomicAdd(&hpos[k * NB + bp], 1u);
                    } else {
                        int bn = min((int)g, NB - 1);
                        if (bn > 0)
                            atomicAdd(&sh[k * (NB / 2) + (bn >> 1)],
                                      1u << ((bn & 1) << 4));
                    }
                }
            }
        }
    }
    __syncthreads();

    // flush private hist DIRECTLY into global hist: atomics only on nonzero words
    #pragma unroll
    for (int i = 0; i < HW / 256; i++) {
        int w = tid + i * 256;              // packed word = k*(NB/2) + (bin>>1)
        unsigned v = sh[w];
        if (v) {
            int k    = w >> 10;             // NB/2 = 1024 words per k
            int bin2 = (w & 1023) * 2;
            unsigned lo = v & 0xffffu, hi = v >> 16;
            unsigned* dsth = &hneg[k * NB + bin2];
            if (lo) atomicAdd(dsth,     lo);
            if (hi) atomicAdd(dsth + 1, hi);
        }
    }

    fg = warpSumD(fg); bg = warpSumD(bg);
    __shared__ double wfg[8], wbg[8];
    int wid = tid >> 5, lid = tid & 31;
    if (lid == 0) { wfg[wid] = fg; wbg[wid] = bg; }
    __syncthreads();
    if (wid == 0) {
        double f2s = (lid < 8) ? wfg[lid] : 0.0;
        double b2s = (lid < 8) ? wbg[lid] : 0.0;
        f2s = warpSumD(f2s); b2s = warpSumD(b2s);
        if (lid == 0) { atomicAdd(&d_seedfg[b], f2s); atomicAdd(&d_seedbg[b], b2s); }
    }
}

// ---------------- K3: Lovász, low-sync suffix scan + fused combine + reset (verbatim) ----------------
__global__ void k_lovasz(float* out) {
    int seg = blockIdx.x;
    int tid = threadIdx.x;
    int lane = tid & 31, wid = tid >> 5;
    int Pi = d_cnt[seg];
    float v_out = 0.0f;

    if (Pi > 0) {
        float P = (float)Pi;
        const uint4* hp4 = (const uint4*)(d_histpos + seg * NB);
        const uint4* hn4 = (const uint4*)(d_histneg + seg * NB);
        const int CH = NB / 256;   // 8
        int lo = tid * CH;
        uint4 pa = hp4[2 * tid], pb = hp4[2 * tid + 1];
        uint4 na = hn4[2 * tid], nb2 = hn4[2 * tid + 1];
        int hpv[CH] = {(int)pa.x,(int)pa.y,(int)pa.z,(int)pa.w,
                       (int)pb.x,(int)pb.y,(int)pb.z,(int)pb.w};
        int hnv[CH] = {(int)na.x,(int)na.y,(int)na.z,(int)na.w,
                       (int)nb2.x,(int)nb2.y,(int)nb2.z,(int)nb2.w};
        int cp = 0, cn = 0;
        #pragma unroll
        for (int j = 0; j < CH; j++) { cp += hpv[j]; cn += hnv[j]; }

        int incP = cp, incN = cn;
        #pragma unroll
        for (int o = 1; o < 32; o <<= 1) {
            int tP = __shfl_down_sync(0xffffffffu, incP, o);
            int tN = __shfl_down_sync(0xffffffffu, incN, o);
            if (lane + o < 32) { incP += tP; incN += tN; }
        }
        __shared__ int wP[8], wN[8];
        if (lane == 0) { wP[wid] = incP; wN[wid] = incN; }
        __syncthreads();
        int laterP = 0, laterN = 0;
        #pragma unroll
        for (int u = 0; u < 8; u++) {
            if (u > wid) { laterP += wP[u]; laterN += wN[u]; }
        }
        int supP = incP - cp + laterP;
        int supN = incN - cn + laterN;

        float jsum = 0.0f;
        int p = supP, n = supN;
        #pragma unroll
        for (int j = CH - 1; j >= 0; j--) {
            p += hpv[j]; n += hnv[j];
            if (lo + j >= 1) jsum += __fdividef((float)(p + n), P + (float)n);
        }
        jsum = warpSumF(jsum);
        __shared__ float wj[8];
        if (lane == 0) wj[wid] = jsum;
        __syncthreads();
        if (wid == 0) {
            float v = (lane < 8) ? wj[lane] : 0.0f;
            v = warpSumF(v);
            if (lane == 0) v_out = v;
        }
    }

    __shared__ int is_fin;
    if (tid == 0) {
        d_inst[seg] = (Pi > 0) ? ((double)v_out + 0.5) * (2.0 / (double)NB) : 0.0;
        __threadfence();
        int prev = atomicAdd(&d_done, 1);
        is_fin = (prev == NSEG - 1) ? 1 : 0;
    }
    __syncthreads();
    if (is_fin) {
        if (tid == 0) {
            double tot = 0.0;
            for (int b = 0; b < BB; b++) {
                double obj = 0.0, il = 0.0, vl = 0.0;
                for (int k = 0; k < KM; k++) {
                    int s = b * KM + k;
                    double pr = (double)d_pres[s];
                    obj += pr;
                    il += d_inst[s] * pr;
                    vl += (double)d_var[s] * pr;
                }
                double so = obj > 0.0 ? obj : 1.0;
                double seedl = (d_seedbg[b] + d_seedfg[b]) / (double)(HH * WW);
                tot += (il / so) + 10.0 * (vl / so) + seedl;
            }
            out[0] = (float)(tot / (double)BB);
            d_done = 0;
        }
        if (tid < NSEG) {
            d_cnt[tid] = 0; d_sit[tid] = 0; d_siy[tid] = 0; d_six[tid] = 0;
            d_ssig[tid] = 0.0; d_ssig2[tid] = 0.0;
        }
    }
}

// ---------------- launch ----------------
extern "C" void kernel_launch(void* const* d_in, const int* in_sizes, int n_in,
                              void* d_out, int out_size) {
    const float* pred = (const float*)d_in[0];
    const int*   inst = (const int*)d_in[1];
    (void)in_sizes; (void)n_in; (void)out_size;

    dim3 g1(SG, BB);
    k_stats<<<g1, 256>>>(pred, inst);

    dim3 g3(CHUNKS, BB);
    k_main<<<g3, 256>>>(pred, inst);

    k_lovasz<<<NSEG, 256>>>((float*)d_out);
}